// round 3
// baseline (speedup 1.0000x reference)
#include <cuda_runtime.h>
#include <math.h>

#define H_  128
#define W_  128
#define HW  16384
#define C_  64
#define T_  16
#define N_  2
#define K3  576
#define K1  192
#define FB  ((long)T_ * C_ * HW)     // feature batch stride
#define FLB ((long)T_ * 2 * HW)      // flow batch stride

// ---------------- scratch (device globals; allocation-free rule) -----------
__device__ float g_comb  [N_ * 3 * C_ * HW];   // [a2 | a1 | x] per batch
__device__ float g_infeat[N_ * C_ * HW];
__device__ float g_h1    [N_ * C_ * HW];

// packed fp32x2 FMA: per-lane IEEE fp32, bitwise identical to scalar FFMA
#define FMA2(c, a, b) \
    asm("fma.rn.f32x2 %0, %1, %2, %0;" : "+l"(c) : "l"(a), "l"(b))

union U64F2 { unsigned long long u; float2 f; };

// ---------------- bilinear helper ------------------------------------------
struct Bil { int i00, i01, i10, i11; float w00, w01, w10, w11; };

__device__ __forceinline__ Bil make_bil(float gx, float gy) {
    Bil b;
    float xf = floorf(gx), yf = floorf(gy);
    float wx = gx - xf,  wy = gy - yf;
    int x0 = (int)xf, y0 = (int)yf;
    int x1 = x0 + 1,  y1 = y0 + 1;
    bool vx0 = (unsigned)x0 < W_, vx1 = (unsigned)x1 < W_;
    bool vy0 = (unsigned)y0 < H_, vy1 = (unsigned)y1 < H_;
    int cx0 = min(max(x0, 0), W_ - 1), cx1 = min(max(x1, 0), W_ - 1);
    int cy0 = min(max(y0, 0), H_ - 1), cy1 = min(max(y1, 0), H_ - 1);
    b.i00 = cy0 * W_ + cx0;  b.i01 = cy0 * W_ + cx1;
    b.i10 = cy1 * W_ + cx0;  b.i11 = cy1 * W_ + cx1;
    b.w00 = (vx0 && vy0) ? (1.f - wx) * (1.f - wy) : 0.f;
    b.w01 = (vx1 && vy0) ? wx * (1.f - wy)         : 0.f;
    b.w10 = (vx0 && vy1) ? (1.f - wx) * wy         : 0.f;
    b.w11 = (vx1 && vy1) ? wx * wy                 : 0.f;
    return b;
}

__device__ __forceinline__ float gath(const float* __restrict__ p, const Bil& b) {
    return b.w00 * __ldg(p + b.i00) + b.w01 * __ldg(p + b.i01)
         + b.w10 * __ldg(p + b.i10) + b.w11 * __ldg(p + b.i11);
}

// ---------------- kernel 1: warp + compose + build comb --------------------
// comb[nb] = [ a2 (64ch) | a1 (64ch) | x (64ch) ]; f1/f2 == nullptr -> zero flow
__global__ void __launch_bounds__(256)
warp_combine_kernel(const float* __restrict__ y2,
                    const float* __restrict__ y1,
                    const float* __restrict__ f1,
                    const float* __restrict__ f2,
                    const float* __restrict__ x)
{
    int p  = blockIdx.x * 256 + threadIdx.x;
    int nb = blockIdx.y;
    int ix = p & (W_ - 1);
    int iy = p >> 7;

    const float* y1n = y1 + nb * FB;
    const float* y2n = y2 + nb * FB;
    const float* xn  = x  + nb * FB;
    float*       cm  = g_comb + (long)nb * 3 * C_ * HW;

    float f1x = 0.f, f1y = 0.f;
    if (f1) {
        const float* f1n = f1 + nb * FLB;
        f1x = f1n[p]; f1y = f1n[HW + p];
    }
    Bil b1 = make_bil((float)ix + f1x, (float)iy + f1y);

    float fcx = f1x, fcy = f1y;
    if (f2) {
        const float* f2n = f2 + nb * FLB;
        fcx += gath(f2n,      b1);
        fcy += gath(f2n + HW, b1);
    }
    Bil b2 = make_bil((float)ix + fcx, (float)iy + fcy);

    #pragma unroll 4
    for (int c = 0; c < C_; c++) {
        cm[c * HW + p]            = gath(y2n + c * HW, b2);   // a2
        cm[(C_ + c) * HW + p]     = gath(y1n + c * HW, b1);   // a1
        cm[(2 * C_ + c) * HW + p] = xn[c * HW + p];           // x
    }
}

// ---------------- GEMM kernel: 64oc x 128px tile, f32x2, double-buffered ----
// MODE 0: 1x1, in g_comb,   out g_infeat, bias only
// MODE 1: 3x3, in g_infeat, out g_h1,     leaky_relu(0.1)
// MODE 2: 3x3, in g_h1,     out d_out,    + residual
// Thread map (256 threads): tx = tid&15 (px), ty = tid>>4 (oc)
//   per-thread oc rows: {2ty, 2ty+1, 32+2ty, 32+2ty+1}
//   per-thread px cols: {4tx..4tx+3, 64+4tx..64+4tx+3}
// As2 holds duplicated weights so LDS.128 yields ready {w,w} f32x2 operands:
//   word index for oc: (oc&31)*2 + (oc>>5)*64
template<int KTOT, int MODE>
__global__ void __launch_bounds__(256)
gemm_kernel(const float* __restrict__ Wt, const float* __restrict__ bias,
            const float* __restrict__ resid, float* __restrict__ outp)
{
    __shared__ float As2[2][16][128];
    __shared__ float Bs [2][16][128];

    const int nb  = blockIdx.y;
    const int px0 = blockIdx.x * 128;
    const int iy  = blockIdx.x;          // 3x3: one image row per block (W==128)
    const int tid = threadIdx.x;
    const int tx  = tid & 15;
    const int ty  = tid >> 4;

    const float* Bin =
        (MODE == 0 ? g_comb + (long)nb * 3 * C_ * HW
                   : (MODE == 1 ? g_infeat : g_h1) + (long)nb * C_ * HW);

    // ---- staging roles ----
    const int oc_l = tid >> 2;            // 0..63  (A loader)
    const int kq   = (tid & 3) * 4;       // k rows kq..kq+3
    const int w0   = ((oc_l & 31) << 1) | ((oc_l >> 5) << 6);
    const int kr   = tid >> 4;            // 0..15  (B loader row)
    const int c0   = (tid & 15) * 8;      // B loader col base

    float4 aS;
    float  bS[8];

    auto loadA = [&](int k0) {
        aS = *(const float4*)(Wt + (size_t)oc_l * KTOT + k0 + kq);
    };
    auto loadB = [&](int k0) {
        if (MODE == 0) {
            const float* src = Bin + (size_t)(k0 + kr) * HW + px0 + c0;
            float4 v0 = *(const float4*)src;
            float4 v1 = *(const float4*)(src + 4);
            bS[0]=v0.x; bS[1]=v0.y; bS[2]=v0.z; bS[3]=v0.w;
            bS[4]=v1.x; bS[5]=v1.y; bS[6]=v1.z; bS[7]=v1.w;
        } else {
            int k   = k0 + kr;
            int ic  = k / 9;
            int tap = k - ic * 9;
            int t3  = tap / 3;
            int dy  = t3 - 1;
            int dx  = tap - t3 * 3 - 1;
            int gy  = iy + dy;
            bool vy = (unsigned)gy < H_;
            const float* src = Bin + (size_t)ic * HW + gy * W_;
            #pragma unroll
            for (int u = 0; u < 8; u++) {
                int gx = c0 + u + dx;
                bS[u] = (vy && (unsigned)gx < W_) ? __ldg(src + gx) : 0.f;
            }
        }
    };
    auto stage = [&](int buf) {
        As2[buf][kq + 0][w0] = aS.x; As2[buf][kq + 0][w0 + 1] = aS.x;
        As2[buf][kq + 1][w0] = aS.y; As2[buf][kq + 1][w0 + 1] = aS.y;
        As2[buf][kq + 2][w0] = aS.z; As2[buf][kq + 2][w0 + 1] = aS.z;
        As2[buf][kq + 3][w0] = aS.w; As2[buf][kq + 3][w0 + 1] = aS.w;
        *(float4*)&Bs[buf][kr][c0]     = make_float4(bS[0], bS[1], bS[2], bS[3]);
        *(float4*)&Bs[buf][kr][c0 + 4] = make_float4(bS[4], bS[5], bS[6], bS[7]);
    };

    unsigned long long acc[4][4];
    #pragma unroll
    for (int i = 0; i < 4; i++)
        #pragma unroll
        for (int j = 0; j < 4; j++) acc[i][j] = 0ull;

    constexpr int NT = KTOT / 16;

    loadA(0); loadB(0);
    stage(0);
    __syncthreads();

    for (int t = 0; t < NT; t++) {
        int cur = t & 1;
        if (t + 1 < NT) { loadA((t + 1) * 16); loadB((t + 1) * 16); }

        #pragma unroll
        for (int k = 0; k < 16; k++) {
            const float* Ak = &As2[cur][k][0];
            const float* Bk = &Bs [cur][k][0];
            ulonglong2 a0 = *(const ulonglong2*)(Ak + 4 * ty);
            ulonglong2 a1 = *(const ulonglong2*)(Ak + 64 + 4 * ty);
            ulonglong2 b0 = *(const ulonglong2*)(Bk + 4 * tx);
            ulonglong2 b1 = *(const ulonglong2*)(Bk + 64 + 4 * tx);
            FMA2(acc[0][0], a0.x, b0.x); FMA2(acc[0][1], a0.x, b0.y);
            FMA2(acc[0][2], a0.x, b1.x); FMA2(acc[0][3], a0.x, b1.y);
            FMA2(acc[1][0], a0.y, b0.x); FMA2(acc[1][1], a0.y, b0.y);
            FMA2(acc[1][2], a0.y, b1.x); FMA2(acc[1][3], a0.y, b1.y);
            FMA2(acc[2][0], a1.x, b0.x); FMA2(acc[2][1], a1.x, b0.y);
            FMA2(acc[2][2], a1.x, b1.x); FMA2(acc[2][3], a1.x, b1.y);
            FMA2(acc[3][0], a1.y, b0.x); FMA2(acc[3][1], a1.y, b0.y);
            FMA2(acc[3][2], a1.y, b1.x); FMA2(acc[3][3], a1.y, b1.y);
        }

        if (t + 1 < NT) stage(1 - cur);
        __syncthreads();
    }

    // ---- epilogue ----
    float* Obase =
        (MODE == 0 ? g_infeat + (long)nb * C_ * HW
         : MODE == 1 ? g_h1   + (long)nb * C_ * HW
                     : outp   + nb * FB);

    const int ocA = 2 * ty;          // rows for i=0,1
    const int ocB = 32 + 2 * ty;     // rows for i=2,3
    float bvs[4] = { bias[ocA], bias[ocA + 1], bias[ocB], bias[ocB + 1] };

    #pragma unroll
    for (int i = 0; i < 4; i++) {
        int oc = (i < 2) ? (ocA + i) : (ocB + (i - 2));
        float bv = bvs[i];
        #pragma unroll
        for (int half = 0; half < 2; half++) {
            U64F2 p0, p1;
            p0.u = acc[i][2 * half];
            p1.u = acc[i][2 * half + 1];
            int px = px0 + half * 64 + 4 * tx;
            float4 v;
            v.x = p0.f.x + bv; v.y = p0.f.y + bv;
            v.z = p1.f.x + bv; v.w = p1.f.y + bv;
            if (MODE == 1) {
                v.x = v.x > 0.f ? v.x : 0.1f * v.x;
                v.y = v.y > 0.f ? v.y : 0.1f * v.y;
                v.z = v.z > 0.f ? v.z : 0.1f * v.z;
                v.w = v.w > 0.f ? v.w : 0.1f * v.w;
            } else if (MODE == 2) {
                float4 r = *(const float4*)(resid + nb * FB + (size_t)oc * HW + px);
                v.x += r.x; v.y += r.y; v.z += r.z; v.w += r.w;
            }
            *(float4*)(Obase + (size_t)oc * HW + px) = v;
        }
    }
}

// ---------------- launcher --------------------------------------------------
extern "C" void kernel_launch(void* const* d_in, const int* in_sizes, int n_in,
                              void* d_out, int out_size)
{
    const float* curr  = (const float*)d_in[0];   // (n,t,c,h,w)
    const float* flows = (const float*)d_in[1];   // (n,t,2,h,w)
    const float* Wfc   = (const float*)d_in[2];   // (c,3c,1,1)
    const float* bfc   = (const float*)d_in[3];
    const float* W1    = (const float*)d_in[4];   // (c,c,3,3)
    const float* b1    = (const float*)d_in[5];
    const float* W2    = (const float*)d_in[6];
    const float* b2    = (const float*)d_in[7];
    float*       out   = (float*)d_out;           // (n,t,c,h,w)

    dim3 warpGrid(HW / 256, N_);
    dim3 gemmGrid(HW / 128, N_);

    for (int t = 0; t < T_; t++) {
        const float* xt = curr + (size_t)t * C_ * HW;
        const float* y1 = (t == 0) ? curr : out + (size_t)(t - 1) * C_ * HW;
        const float* y2 = (t <= 1) ? curr : out + (size_t)(t - 2) * C_ * HW;
        const float* f1 = (t >= 1) ? flows + (size_t)(t - 1) * 2 * HW : nullptr;
        const float* f2 = (t >= 2) ? flows + (size_t)(t - 2) * 2 * HW : nullptr;
        float*       ot = out + (size_t)t * C_ * HW;

        warp_combine_kernel<<<warpGrid, 256>>>(y2, y1, f1, f2, xt);
        gemm_kernel<K1, 0><<<gemmGrid, 256>>>(Wfc, bfc, nullptr, nullptr);
        gemm_kernel<K3, 1><<<gemmGrid, 256>>>(W1, b1, nullptr, nullptr);
        gemm_kernel<K3, 2><<<gemmGrid, 256>>>(W2, b2, xt, ot);
    }
}

// round 8
// speedup vs baseline: 1.4381x; 1.4381x over previous
#include <cuda_runtime.h>
#include <math.h>

#define H_  128
#define W_  128
#define HW  16384
#define C_  64
#define T_  16
#define N_  2
#define K3  576
#define K1  192
#define FB  ((long)T_ * C_ * HW)     // feature batch stride
#define FLB ((long)T_ * 2 * HW)      // flow batch stride

// ---------------- scratch (device globals; allocation-free rule) -----------
__device__ float g_comb  [N_ * 3 * C_ * HW];   // [a2 | a1 | x] per batch
__device__ float g_infeat[N_ * C_ * HW];
__device__ float g_h1    [N_ * C_ * HW];

// packed fp32x2 FMA: per-lane IEEE fp32, bitwise identical to scalar FFMA
#define FMA2(c, a, b) \
    asm("fma.rn.f32x2 %0, %1, %2, %0;" : "+l"(c) : "l"(a), "l"(b))

union U64F2 { unsigned long long u; float2 f; };

// ---------------- bilinear helper ------------------------------------------
struct Bil { int i00, i01, i10, i11; float w00, w01, w10, w11; };

__device__ __forceinline__ Bil make_bil(float gx, float gy) {
    Bil b;
    float xf = floorf(gx), yf = floorf(gy);
    float wx = gx - xf,  wy = gy - yf;
    int x0 = (int)xf, y0 = (int)yf;
    int x1 = x0 + 1,  y1 = y0 + 1;
    bool vx0 = (unsigned)x0 < W_, vx1 = (unsigned)x1 < W_;
    bool vy0 = (unsigned)y0 < H_, vy1 = (unsigned)y1 < H_;
    int cx0 = min(max(x0, 0), W_ - 1), cx1 = min(max(x1, 0), W_ - 1);
    int cy0 = min(max(y0, 0), H_ - 1), cy1 = min(max(y1, 0), H_ - 1);
    b.i00 = cy0 * W_ + cx0;  b.i01 = cy0 * W_ + cx1;
    b.i10 = cy1 * W_ + cx0;  b.i11 = cy1 * W_ + cx1;
    b.w00 = (vx0 && vy0) ? (1.f - wx) * (1.f - wy) : 0.f;
    b.w01 = (vx1 && vy0) ? wx * (1.f - wy)         : 0.f;
    b.w10 = (vx0 && vy1) ? (1.f - wx) * wy         : 0.f;
    b.w11 = (vx1 && vy1) ? wx * wy                 : 0.f;
    return b;
}

__device__ __forceinline__ float gath(const float* __restrict__ p, const Bil& b) {
    return b.w00 * __ldg(p + b.i00) + b.w01 * __ldg(p + b.i01)
         + b.w10 * __ldg(p + b.i10) + b.w11 * __ldg(p + b.i11);
}

// ---------------- kernel 1: warp + compose + build comb --------------------
__global__ void __launch_bounds__(256)
warp_combine_kernel(const float* __restrict__ y2,
                    const float* __restrict__ y1,
                    const float* __restrict__ f1,
                    const float* __restrict__ f2,
                    const float* __restrict__ x)
{
    int p  = blockIdx.x * 256 + threadIdx.x;
    int nb = blockIdx.y;
    int ix = p & (W_ - 1);
    int iy = p >> 7;

    const float* y1n = y1 + nb * FB;
    const float* y2n = y2 + nb * FB;
    const float* xn  = x  + nb * FB;
    float*       cm  = g_comb + (long)nb * 3 * C_ * HW;

    float f1x = 0.f, f1y = 0.f;
    if (f1) {
        const float* f1n = f1 + nb * FLB;
        f1x = f1n[p]; f1y = f1n[HW + p];
    }
    Bil b1 = make_bil((float)ix + f1x, (float)iy + f1y);

    float fcx = f1x, fcy = f1y;
    if (f2) {
        const float* f2n = f2 + nb * FLB;
        fcx += gath(f2n,      b1);
        fcy += gath(f2n + HW, b1);
    }
    Bil b2 = make_bil((float)ix + fcx, (float)iy + fcy);

    #pragma unroll 4
    for (int c = 0; c < C_; c++) {
        cm[c * HW + p]            = gath(y2n + c * HW, b2);   // a2
        cm[(C_ + c) * HW + p]     = gath(y1n + c * HW, b1);   // a1
        cm[(2 * C_ + c) * HW + p] = xn[c * HW + p];           // x
    }
}

// ---------------- GEMM: 64oc x 128px CTA tile, 128 threads, 8x8/thread ------
// MODE 0: 1x1, in g_comb,   out g_infeat, bias only
// MODE 1: 3x3, in g_infeat, out g_h1,     leaky_relu(0.1)
// MODE 2: 3x3, in g_h1,     out d_out,    + residual
// Thread map: tx = tid&15 (8 px each), ty = tid>>4 (0..7, 8 oc each).
// As2 duplicated weights: As2[k][2*oc] = As2[k][2*oc+1] = W[oc][k], so a
// thread's 8 oc rows are one contiguous 64B run -> 4x LDS.128 of {w,w} pairs.
template<int KTOT, int MODE>
__global__ void __launch_bounds__(128)
gemm_kernel(const float* __restrict__ Wt, const float* __restrict__ bias,
            const float* __restrict__ resid, float* __restrict__ outp)
{
    __shared__ float As2[2][16][128];
    __shared__ float Bs [2][16][128];

    const int nb  = blockIdx.y;
    const int px0 = blockIdx.x * 128;
    const int iy  = blockIdx.x;          // 3x3: one image row per block (W==128)
    const int tid = threadIdx.x;
    const int tx  = tid & 15;
    const int ty  = tid >> 4;            // 0..7

    const float* Bin =
        (MODE == 0 ? g_comb + (long)nb * 3 * C_ * HW
                   : (MODE == 1 ? g_infeat : g_h1) + (long)nb * C_ * HW);

    // ---- staging roles (128 threads) ----
    const int oc_a = tid & 63;           // A loader: one oc, 8 k rows
    const int kh   = (tid >> 6) * 8;     // 0 or 8
    const int kr   = tid >> 3;           // B loader: k row 0..15
    const int c0   = (tid & 7) * 16;     // B loader: 16 px

    float aS[8];
    float bS[16];

    auto loadA = [&](int k0) {
        const float* src = Wt + (size_t)oc_a * KTOT + k0 + kh;
        float4 v0 = *(const float4*)src;
        float4 v1 = *(const float4*)(src + 4);
        aS[0]=v0.x; aS[1]=v0.y; aS[2]=v0.z; aS[3]=v0.w;
        aS[4]=v1.x; aS[5]=v1.y; aS[6]=v1.z; aS[7]=v1.w;
    };
    auto loadB = [&](int k0) {
        if (MODE == 0) {
            const float* src = Bin + (size_t)(k0 + kr) * HW + px0 + c0;
            #pragma unroll
            for (int u = 0; u < 4; u++) {
                float4 v = *(const float4*)(src + 4 * u);
                bS[4*u+0]=v.x; bS[4*u+1]=v.y; bS[4*u+2]=v.z; bS[4*u+3]=v.w;
            }
        } else {
            int k   = k0 + kr;
            int ic  = k / 9;
            int tap = k - ic * 9;
            int t3  = tap / 3;
            int dy  = t3 - 1;
            int dx  = tap - t3 * 3 - 1;
            int gy  = iy + dy;
            bool vy = (unsigned)gy < H_;
            const float* src = Bin + (size_t)ic * HW + gy * W_;
            #pragma unroll
            for (int u = 0; u < 16; u++) {
                int gx = c0 + u + dx;
                bS[u] = (vy && (unsigned)gx < W_) ? __ldg(src + gx) : 0.f;
            }
        }
    };
    auto stage = [&](int buf) {
        #pragma unroll
        for (int u = 0; u < 8; u++)
            *(float2*)&As2[buf][kh + u][2 * oc_a] = make_float2(aS[u], aS[u]);
        #pragma unroll
        for (int u = 0; u < 4; u++)
            *(float4*)&Bs[buf][kr][c0 + 4 * u] =
                make_float4(bS[4*u], bS[4*u+1], bS[4*u+2], bS[4*u+3]);
    };

    unsigned long long acc[8][4];
    #pragma unroll
    for (int i = 0; i < 8; i++)
        #pragma unroll
        for (int j = 0; j < 4; j++) acc[i][j] = 0ull;

    constexpr int NT = KTOT / 16;

    loadA(0); loadB(0);
    stage(0);
    __syncthreads();

    for (int t = 0; t < NT; t++) {
        int cur = t & 1;
        if (t + 1 < NT) { loadA((t + 1) * 16); loadB((t + 1) * 16); }

        #pragma unroll
        for (int k = 0; k < 16; k++) {
            const float* Ak = &As2[cur][k][16 * ty];
            const float* Bk = &Bs [cur][k][8 * tx];
            ulonglong2 a01 = *(const ulonglong2*)(Ak);
            ulonglong2 a23 = *(const ulonglong2*)(Ak + 4);
            ulonglong2 a45 = *(const ulonglong2*)(Ak + 8);
            ulonglong2 a67 = *(const ulonglong2*)(Ak + 12);
            ulonglong2 b01 = *(const ulonglong2*)(Bk);
            ulonglong2 b23 = *(const ulonglong2*)(Bk + 4);
            unsigned long long av[8] = {a01.x, a01.y, a23.x, a23.y,
                                        a45.x, a45.y, a67.x, a67.y};
            unsigned long long bv[4] = {b01.x, b01.y, b23.x, b23.y};
            #pragma unroll
            for (int i = 0; i < 8; i++) {
                FMA2(acc[i][0], av[i], bv[0]);
                FMA2(acc[i][1], av[i], bv[1]);
                FMA2(acc[i][2], av[i], bv[2]);
                FMA2(acc[i][3], av[i], bv[3]);
            }
        }

        if (t + 1 < NT) stage(1 - cur);
        __syncthreads();
    }

    // ---- epilogue: 8 oc x 8 px per thread ----
    float* Obase =
        (MODE == 0 ? g_infeat + (long)nb * C_ * HW
         : MODE == 1 ? g_h1   + (long)nb * C_ * HW
                     : outp   + nb * FB);

    #pragma unroll
    for (int i = 0; i < 8; i++) {
        int oc = 8 * ty + i;
        float bv = __ldg(bias + oc);
        float* O = Obase + (size_t)oc * HW + px0 + 8 * tx;
        float v[8];
        #pragma unroll
        for (int j = 0; j < 4; j++) {
            U64F2 p; p.u = acc[i][j];
            v[2*j]   = p.f.x + bv;
            v[2*j+1] = p.f.y + bv;
        }
        if (MODE == 1) {
            #pragma unroll
            for (int j = 0; j < 8; j++)
                v[j] = v[j] > 0.f ? v[j] : 0.1f * v[j];
        } else if (MODE == 2) {
            const float* R = resid + nb * FB + (size_t)oc * HW + px0 + 8 * tx;
            float4 r0 = *(const float4*)R;
            float4 r1 = *(const float4*)(R + 4);
            v[0]+=r0.x; v[1]+=r0.y; v[2]+=r0.z; v[3]+=r0.w;
            v[4]+=r1.x; v[5]+=r1.y; v[6]+=r1.z; v[7]+=r1.w;
        }
        *(float4*)O       = make_float4(v[0], v[1], v[2], v[3]);
        *(float4*)(O + 4) = make_float4(v[4], v[5], v[6], v[7]);
    }
}

// ---------------- launcher --------------------------------------------------
extern "C" void kernel_launch(void* const* d_in, const int* in_sizes, int n_in,
                              void* d_out, int out_size)
{
    const float* curr  = (const float*)d_in[0];   // (n,t,c,h,w)
    const float* flows = (const float*)d_in[1];   // (n,t,2,h,w)
    const float* Wfc   = (const float*)d_in[2];   // (c,3c,1,1)
    const float* bfc   = (const float*)d_in[3];
    const float* W1    = (const float*)d_in[4];   // (c,c,3,3)
    const float* b1    = (const float*)d_in[5];
    const float* W2    = (const float*)d_in[6];
    const float* b2    = (const float*)d_in[7];
    float*       out   = (float*)d_out;           // (n,t,c,h,w)

    dim3 warpGrid(HW / 256, N_);
    dim3 gemmGrid(HW / 128, N_);

    for (int t = 0; t < T_; t++) {
        const float* xt = curr + (size_t)t * C_ * HW;
        const float* y1 = (t == 0) ? curr : out + (size_t)(t - 1) * C_ * HW;
        const float* y2 = (t <= 1) ? curr : out + (size_t)(t - 2) * C_ * HW;
        const float* f1 = (t >= 1) ? flows + (size_t)(t - 1) * 2 * HW : nullptr;
        const float* f2 = (t >= 2) ? flows + (size_t)(t - 2) * 2 * HW : nullptr;
        float*       ot = out + (size_t)t * C_ * HW;

        warp_combine_kernel<<<warpGrid, 256>>>(y2, y1, f1, f2, xt);
        gemm_kernel<K1, 0><<<gemmGrid, 128>>>(Wfc, bfc, nullptr, nullptr);
        gemm_kernel<K3, 1><<<gemmGrid, 128>>>(W1, b1, nullptr, nullptr);
        gemm_kernel<K3, 2><<<gemmGrid, 128>>>(W2, b2, xt, ot);
    }
}